// round 9
// baseline (speedup 1.0000x reference)
#include <cuda_runtime.h>
#include <math.h>

// ---------------- problem constants ----------------
#define NB    4
#define S_LEN 2048
#define DIM   512
#define NH    8
#define HD    64
#define TOK   (NB * S_LEN)          // 8192

// ---------------- scratch (no allocations allowed) ----------------
__device__ float g_h[TOK * DIM];          // LN output (reused for LN1 and LN2)
__device__ float g_qkv[TOK * 3 * DIM];    // QKV, rope applied in-place
__device__ float g_att[TOK * DIM];        // attention output (b,s,h,d)
__device__ float g_x1[TOK * DIM];         // residual after proj
__device__ float g_mid[TOK * 4 * DIM];    // FC1/GELU output

// ---------------- LayerNorm: one block (256 thr) per row of 512 ----------------
__global__ void __launch_bounds__(256) ln_kernel(const float* __restrict__ x,
                                                 const float* __restrict__ g,
                                                 const float* __restrict__ b,
                                                 float* __restrict__ out)
{
    int row = blockIdx.x;
    int t = threadIdx.x;                       // 0..255, 2 elems each
    const float2* xr = (const float2*)(x + (size_t)row * DIM);
    float2 v = xr[t];
    float s = v.x + v.y;
    float ss = v.x * v.x + v.y * v.y;
#pragma unroll
    for (int m = 16; m; m >>= 1) {
        s  += __shfl_xor_sync(0xffffffffu, s, m);
        ss += __shfl_xor_sync(0xffffffffu, ss, m);
    }
    __shared__ float sh[16];
    int w = t >> 5;
    if ((t & 31) == 0) { sh[w] = s; sh[8 + w] = ss; }
    __syncthreads();
    s = 0.f; ss = 0.f;
#pragma unroll
    for (int i = 0; i < 8; i++) { s += sh[i]; ss += sh[8 + i]; }
    float mu  = s * (1.f / DIM);
    float var = ss * (1.f / DIM) - mu * mu;
    float inv = rsqrtf(var + 1e-5f);
    float2 gg = ((const float2*)g)[t];
    float2 bb = ((const float2*)b)[t];
    float2 o;
    o.x = (v.x - mu) * inv * gg.x + bb.x;
    o.y = (v.y - mu) * inv * gg.y + bb.y;
    ((float2*)(out + (size_t)row * DIM))[t] = o;
}

// ---------------- RoPE applied in-place to q and k slices of qkv ----------------
// thread t -> (token, head, d) with d in [0,32); handles pair (d, d+32) of q and k
__global__ void __launch_bounds__(256) rope_kernel(float* __restrict__ qkv,
                                                   const float* __restrict__ cb,
                                                   const float* __restrict__ sb)
{
    int t = blockIdx.x * blockDim.x + threadIdx.x;   // 0 .. TOK*NH*32-1
    if (t >= TOK * NH * 32) return;
    int d   = t & 31;
    int h   = (t >> 5) & 7;
    int tok = t >> 8;
    int s   = tok & (S_LEN - 1);
    float c0 = cb[s * HD + d],      c1 = cb[s * HD + d + 32];
    float s0 = sb[s * HD + d],      s1 = sb[s * HD + d + 32];
    float* row = qkv + (size_t)tok * (3 * DIM);
    float* q = row + h * HD;
    float q0 = q[d], q1 = q[d + 32];
    q[d]      = q0 * c0 - q1 * s0;
    q[d + 32] = q1 * c1 + q0 * s1;
    float* k = row + DIM + h * HD;
    float k0 = k[d], k1 = k[d + 32];
    k[d]      = k0 * c0 - k1 * s0;
    k[d + 32] = k1 * c1 + k0 * s1;
}

// ---------------- generic tiled GEMM with fused epilogue ----------------
// C[M,N] = A[M,K] @ B[K,N] + bias   (EPI==1: gelu; EPI==2: += R)
// BM=BN=64, BK=16, 128 threads, 4x8 micro-tile per thread
__device__ __forceinline__ float gelu_f(float x)
{
    return 0.5f * x * (1.f + erff(x * 0.7071067811865476f));
}

template <int EPI>
__global__ void __launch_bounds__(128) gemm_kernel(const float* __restrict__ A,
                                                   const float* __restrict__ B,
                                                   const float* __restrict__ bias,
                                                   const float* __restrict__ R,
                                                   float* __restrict__ C,
                                                   int M, int N, int K)
{
    __shared__ __align__(16) float As[16][68];   // transposed: As[k][m]
    __shared__ __align__(16) float Bs[16][64];

    int tid = threadIdx.x;
    int tx = tid & 7, ty = tid >> 3;
    int m0 = blockIdx.y * 64, n0 = blockIdx.x * 64;

    float acc[4][8];
#pragma unroll
    for (int i = 0; i < 4; i++)
#pragma unroll
        for (int j = 0; j < 8; j++) acc[i][j] = 0.f;

    for (int k0 = 0; k0 < K; k0 += 16) {
        // A tile 64x16 (256 float4), stored transposed
#pragma unroll
        for (int it = 0; it < 2; ++it) {
            int i = tid + it * 128;
            int r = i >> 2, c = i & 3;
            float4 v = *(const float4*)&A[(size_t)(m0 + r) * K + k0 + c * 4];
            As[c * 4 + 0][r] = v.x; As[c * 4 + 1][r] = v.y;
            As[c * 4 + 2][r] = v.z; As[c * 4 + 3][r] = v.w;
        }
        // B tile 16x64 (256 float4)
#pragma unroll
        for (int it = 0; it < 2; ++it) {
            int i = tid + it * 128;
            int r = i >> 4, c = i & 15;
            *(float4*)&Bs[r][c * 4] = *(const float4*)&B[(size_t)(k0 + r) * N + n0 + c * 4];
        }
        __syncthreads();
#pragma unroll
        for (int k = 0; k < 16; k++) {
            float4 a  = *(const float4*)&As[k][ty * 4];
            float4 b0 = *(const float4*)&Bs[k][tx * 8];
            float4 b1 = *(const float4*)&Bs[k][tx * 8 + 4];
            float av[4] = {a.x, a.y, a.z, a.w};
            float bv[8] = {b0.x, b0.y, b0.z, b0.w, b1.x, b1.y, b1.z, b1.w};
#pragma unroll
            for (int i = 0; i < 4; i++)
#pragma unroll
                for (int j = 0; j < 8; j++) acc[i][j] += av[i] * bv[j];
        }
        __syncthreads();
    }

    // epilogue
    float4 bias0 = *(const float4*)&bias[n0 + tx * 8];
    float4 bias1 = *(const float4*)&bias[n0 + tx * 8 + 4];
    float bb[8] = {bias0.x, bias0.y, bias0.z, bias0.w, bias1.x, bias1.y, bias1.z, bias1.w};
#pragma unroll
    for (int i = 0; i < 4; i++) {
        int m = m0 + ty * 4 + i;
        size_t off = (size_t)m * N + n0 + tx * 8;
        float vv[8];
#pragma unroll
        for (int j = 0; j < 8; j++) {
            float v = acc[i][j] + bb[j];
            if (EPI == 1) v = gelu_f(v);
            vv[j] = v;
        }
        if (EPI == 2) {
            float4 r0 = *(const float4*)&R[off];
            float4 r1 = *(const float4*)&R[off + 4];
            vv[0] += r0.x; vv[1] += r0.y; vv[2] += r0.z; vv[3] += r0.w;
            vv[4] += r1.x; vv[5] += r1.y; vv[6] += r1.z; vv[7] += r1.w;
        }
        *(float4*)&C[off]     = make_float4(vv[0], vv[1], vv[2], vv[3]);
        *(float4*)&C[off + 4] = make_float4(vv[4], vv[5], vv[6], vv[7]);
    }
}

// ---------------- flash attention: grid (S/64, NH, NB), 128 threads ----------------
// dynamic smem layout: Qs[64][66] | Kt[64][64] | Vs[64][64] | Ps[64][66]
#define ATT_SMEM_FLOATS (64 * 66 + 64 * 64 + 64 * 64 + 64 * 66)

__global__ void __launch_bounds__(128) attn_kernel(const float* __restrict__ qkv,
                                                   float* __restrict__ out)
{
    extern __shared__ __align__(16) float smem[];
    float (*Qs)[66] = (float(*)[66])(smem);
    float (*Kt)[64] = (float(*)[64])(smem + 64 * 66);
    float (*Vs)[64] = (float(*)[64])(smem + 64 * 66 + 64 * 64);
    float (*Ps)[66] = (float(*)[66])(smem + 64 * 66 + 2 * 64 * 64);

    int tid = threadIdx.x, tx = tid & 7, ty = tid >> 3;
    int qt = blockIdx.x, h = blockIdx.y, b = blockIdx.z;

    const float* base = qkv + (size_t)b * S_LEN * (3 * DIM);
    const float* Qg = base + h * HD;
    const float* Kg = base + DIM + h * HD;
    const float* Vg = base + 2 * DIM + h * HD;

    // load Q tile (64 rows x 64 d)
#pragma unroll
    for (int it = 0; it < 8; ++it) {
        int i = tid + it * 128;
        int r = i >> 4, c = i & 15;
        float4 v = *(const float4*)&Qg[(size_t)(qt * 64 + r) * (3 * DIM) + c * 4];
        Qs[r][c * 4 + 0] = v.x; Qs[r][c * 4 + 1] = v.y;
        Qs[r][c * 4 + 2] = v.z; Qs[r][c * 4 + 3] = v.w;
    }

    float m_r[4], l_r[4], accO[4][8];
#pragma unroll
    for (int i = 0; i < 4; i++) {
        m_r[i] = -1e30f; l_r[i] = 0.f;
#pragma unroll
        for (int j = 0; j < 8; j++) accO[i][j] = 0.f;
    }
    const float scale = 0.125f;   // 1/sqrt(64)

    for (int nt = 0; nt < S_LEN / 64; ++nt) {
        __syncthreads();   // previous PV reads of Kt/Vs done
        // load K (transposed -> Kt[d][col]) and V (Vs[row][d])
#pragma unroll
        for (int it = 0; it < 8; ++it) {
            int i = tid + it * 128;
            int r = i >> 4, c = i & 15;
            size_t go = (size_t)(nt * 64 + r) * (3 * DIM) + c * 4;
            float4 kv = *(const float4*)&Kg[go];
            Kt[c * 4 + 0][r] = kv.x; Kt[c * 4 + 1][r] = kv.y;
            Kt[c * 4 + 2][r] = kv.z; Kt[c * 4 + 3][r] = kv.w;
            *(float4*)&Vs[r][c * 4] = *(const float4*)&Vg[go];
        }
        __syncthreads();

        // S = Q K^T (4x8 per thread)
        float s[4][8];
#pragma unroll
        for (int i = 0; i < 4; i++)
#pragma unroll
            for (int j = 0; j < 8; j++) s[i][j] = 0.f;
#pragma unroll 16
        for (int d = 0; d < 64; ++d) {
            float a0 = Qs[ty * 4 + 0][d], a1 = Qs[ty * 4 + 1][d];
            float a2 = Qs[ty * 4 + 2][d], a3 = Qs[ty * 4 + 3][d];
            float4 k0 = *(const float4*)&Kt[d][tx * 8];
            float4 k1 = *(const float4*)&Kt[d][tx * 8 + 4];
            float kv[8] = {k0.x, k0.y, k0.z, k0.w, k1.x, k1.y, k1.z, k1.w};
#pragma unroll
            for (int j = 0; j < 8; j++) {
                s[0][j] += a0 * kv[j]; s[1][j] += a1 * kv[j];
                s[2][j] += a2 * kv[j]; s[3][j] += a3 * kv[j];
            }
        }

        // online softmax update
#pragma unroll
        for (int i = 0; i < 4; i++) {
            float mt = -1e30f;
#pragma unroll
            for (int j = 0; j < 8; j++) { s[i][j] *= scale; mt = fmaxf(mt, s[i][j]); }
            mt = fmaxf(mt, __shfl_xor_sync(0xffffffffu, mt, 1));
            mt = fmaxf(mt, __shfl_xor_sync(0xffffffffu, mt, 2));
            mt = fmaxf(mt, __shfl_xor_sync(0xffffffffu, mt, 4));
            float mn = fmaxf(m_r[i], mt);
            float alpha = __expf(m_r[i] - mn);
            float rs = 0.f;
#pragma unroll
            for (int j = 0; j < 8; j++) {
                float p = __expf(s[i][j] - mn);
                Ps[ty * 4 + i][tx * 8 + j] = p;
                rs += p;
            }
            rs += __shfl_xor_sync(0xffffffffu, rs, 1);
            rs += __shfl_xor_sync(0xffffffffu, rs, 2);
            rs += __shfl_xor_sync(0xffffffffu, rs, 4);
            l_r[i] = l_r[i] * alpha + rs;
            m_r[i] = mn;
#pragma unroll
            for (int j = 0; j < 8; j++) accO[i][j] *= alpha;
        }
        __syncthreads();   // Ps visible

        // O += P @ V
#pragma unroll 16
        for (int j = 0; j < 64; ++j) {
            float p0 = Ps[ty * 4 + 0][j], p1 = Ps[ty * 4 + 1][j];
            float p2 = Ps[ty * 4 + 2][j], p3 = Ps[ty * 4 + 3][j];
            float4 v0 = *(const float4*)&Vs[j][tx * 8];
            float4 v1 = *(const float4*)&Vs[j][tx * 8 + 4];
            float vv[8] = {v0.x, v0.y, v0.z, v0.w, v1.x, v1.y, v1.z, v1.w};
#pragma unroll
            for (int c = 0; c < 8; c++) {
                accO[0][c] += p0 * vv[c]; accO[1][c] += p1 * vv[c];
                accO[2][c] += p2 * vv[c]; accO[3][c] += p3 * vv[c];
            }
        }
    }

    // write O / l to (b, s, h*HD + d) layout
#pragma unroll
    for (int i = 0; i < 4; i++) {
        float inv = 1.f / l_r[i];
        int row = b * S_LEN + qt * 64 + ty * 4 + i;
        size_t off = (size_t)row * DIM + h * HD + tx * 8;
        *(float4*)&out[off] = make_float4(accO[i][0] * inv, accO[i][1] * inv,
                                          accO[i][2] * inv, accO[i][3] * inv);
        *(float4*)&out[off + 4] = make_float4(accO[i][4] * inv, accO[i][5] * inv,
                                              accO[i][6] * inv, accO[i][7] * inv);
    }
}

// ---------------- launcher ----------------
extern "C" void kernel_launch(void* const* d_in, const int* in_sizes, int n_in,
                              void* d_out, int out_size)
{
    const float* x        = (const float*)d_in[0];
    const float* rope_cos = (const float*)d_in[1];
    const float* rope_sin = (const float*)d_in[2];
    const float* n1g      = (const float*)d_in[3];
    const float* n1b      = (const float*)d_in[4];
    const float* n2g      = (const float*)d_in[5];
    const float* n2b      = (const float*)d_in[6];
    const float* w_qkv    = (const float*)d_in[7];
    const float* b_qkv    = (const float*)d_in[8];
    const float* w_proj   = (const float*)d_in[9];
    const float* b_proj   = (const float*)d_in[10];
    const float* w_fc1    = (const float*)d_in[11];
    const float* b_fc1    = (const float*)d_in[12];
    const float* w_fc2    = (const float*)d_in[13];
    const float* b_fc2    = (const float*)d_in[14];
    float* out = (float*)d_out;

    float *ph, *pqkv, *patt, *px1, *pmid;
    cudaGetSymbolAddress((void**)&ph,   g_h);
    cudaGetSymbolAddress((void**)&pqkv, g_qkv);
    cudaGetSymbolAddress((void**)&patt, g_att);
    cudaGetSymbolAddress((void**)&px1,  g_x1);
    cudaGetSymbolAddress((void**)&pmid, g_mid);

    // opt-in dynamic smem for attention (66.5 KB); idempotent, capture-safe
    cudaFuncSetAttribute(attn_kernel, cudaFuncAttributeMaxDynamicSharedMemorySize,
                         ATT_SMEM_FLOATS * (int)sizeof(float));

    // 1) LN1
    ln_kernel<<<TOK, 256>>>(x, n1g, n1b, ph);
    // 2) QKV GEMM + bias
    gemm_kernel<0><<<dim3(3 * DIM / 64, TOK / 64), 128>>>(ph, w_qkv, b_qkv, nullptr, pqkv,
                                                          TOK, 3 * DIM, DIM);
    // 3) RoPE in place
    rope_kernel<<<(TOK * NH * 32 + 255) / 256, 256>>>(pqkv, rope_cos, rope_sin);
    // 4) attention
    attn_kernel<<<dim3(S_LEN / 64, NH, NB), 128, ATT_SMEM_FLOATS * sizeof(float)>>>(pqkv, patt);
    // 5) proj + bias + residual(x)
    gemm_kernel<2><<<dim3(DIM / 64, TOK / 64), 128>>>(patt, w_proj, b_proj, x, px1,
                                                      TOK, DIM, DIM);
    // 6) LN2
    ln_kernel<<<TOK, 256>>>(px1, n2g, n2b, ph);
    // 7) FC1 + bias + GELU
    gemm_kernel<1><<<dim3(4 * DIM / 64, TOK / 64), 128>>>(ph, w_fc1, b_fc1, nullptr, pmid,
                                                          TOK, 4 * DIM, DIM);
    // 8) FC2 + bias + residual(x1) -> out
    gemm_kernel<2><<<dim3(DIM / 64, TOK / 64), 128>>>(pmid, w_fc2, b_fc2, px1, out,
                                                      TOK, DIM, 4 * DIM);
}

// round 10
// speedup vs baseline: 1.5760x; 1.5760x over previous
#include <cuda_runtime.h>
#include <math.h>

// ---------------- problem constants ----------------
#define NB    4
#define S_LEN 2048
#define DIM   512
#define NH    8
#define HD    64
#define TOK   (NB * S_LEN)          // 8192

// ---------------- scratch (no allocations allowed) ----------------
__device__ float g_h[TOK * DIM];          // LN output (reused for LN1 and LN2)
__device__ float g_qkv[TOK * 3 * DIM];    // QKV (V consumed from here)
__device__ float g_qt[NB * NH * HD * S_LEN];  // Q^T per (b,h): [d][s], rope applied
__device__ float g_kt[NB * NH * HD * S_LEN];  // K^T per (b,h): [d][s], rope applied
__device__ float g_att[TOK * DIM];        // attention output (b,s,h,d)
__device__ float g_x1[TOK * DIM];         // residual after proj
__device__ float g_mid[TOK * 4 * DIM];    // FC1/GELU output

// ---------------- LayerNorm: one block (256 thr) per row of 512 ----------------
__global__ void __launch_bounds__(256) ln_kernel(const float* __restrict__ x,
                                                 const float* __restrict__ g,
                                                 const float* __restrict__ b,
                                                 float* __restrict__ out)
{
    int row = blockIdx.x;
    int t = threadIdx.x;                       // 0..255, 2 elems each
    const float2* xr = (const float2*)(x + (size_t)row * DIM);
    float2 v = xr[t];
    float s = v.x + v.y;
    float ss = v.x * v.x + v.y * v.y;
#pragma unroll
    for (int m = 16; m; m >>= 1) {
        s  += __shfl_xor_sync(0xffffffffu, s, m);
        ss += __shfl_xor_sync(0xffffffffu, ss, m);
    }
    __shared__ float sh[16];
    int w = t >> 5;
    if ((t & 31) == 0) { sh[w] = s; sh[8 + w] = ss; }
    __syncthreads();
    s = 0.f; ss = 0.f;
#pragma unroll
    for (int i = 0; i < 8; i++) { s += sh[i]; ss += sh[8 + i]; }
    float mu  = s * (1.f / DIM);
    float var = ss * (1.f / DIM) - mu * mu;
    float inv = rsqrtf(var + 1e-5f);
    float2 gg = ((const float2*)g)[t];
    float2 bb = ((const float2*)b)[t];
    float2 o;
    o.x = (v.x - mu) * inv * gg.x + bb.x;
    o.y = (v.y - mu) * inv * gg.y + bb.y;
    ((float2*)(out + (size_t)row * DIM))[t] = o;
}

// ---------------- fused RoPE + transpose of Q,K into [bh][d][s] ----------------
// grid (S_LEN/32, NB*NH), 256 threads. Tiled transpose through smem,
// rope applied at write time (partner element available in the smem tile).
__global__ void __launch_bounds__(256) qk_rope_transpose(const float* __restrict__ qkv,
                                                         const float* __restrict__ cb,
                                                         const float* __restrict__ sb,
                                                         float* __restrict__ qt,
                                                         float* __restrict__ kt)
{
    __shared__ float tq[32][65], tk[32][65], tc[32][65], tss[32][65];
    int s0 = blockIdx.x * 32;
    int bh = blockIdx.y;               // b*NH + h
    int b = bh >> 3, h = bh & 7;
    int tid = threadIdx.x;
    int d = tid & 63, sl = tid >> 6;   // 4 s-rows per iter
#pragma unroll
    for (int it = 0; it < 8; it++) {
        int s = sl + it * 4;
        size_t ro = ((size_t)(b * S_LEN + s0 + s)) * (3 * DIM) + h * HD + d;
        tq[s][d]  = qkv[ro];
        tk[s][d]  = qkv[ro + DIM];
        tc[s][d]  = cb[(s0 + s) * HD + d];
        tss[s][d] = sb[(s0 + s) * HD + d];
    }
    __syncthreads();
    int sw = tid & 31, dw = tid >> 5;  // 8 d-rows per iter
#pragma unroll
    for (int it = 0; it < 8; it++) {
        int dd = dw + it * 8;
        float c = tc[sw][dd], sn = tss[sw][dd];
        float q0 = tq[sw][dd], q1 = tq[sw][dd ^ 32];
        float k0 = tk[sw][dd], k1 = tk[sw][dd ^ 32];
        float rq = (dd < 32) ? (q0 * c - q1 * sn) : (q0 * c + q1 * sn);
        float rk = (dd < 32) ? (k0 * c - k1 * sn) : (k0 * c + k1 * sn);
        size_t wo = ((size_t)bh * HD + dd) * S_LEN + s0 + sw;
        qt[wo] = rq;
        kt[wo] = rk;
    }
}

// ---------------- generic tiled GEMM with fused epilogue ----------------
// C[M,N] = A[M,K] @ B[K,N] + bias   (EPI==1: gelu; EPI==2: += R)
// BM=BN=64, BK=16, 128 threads, 4x8 micro-tile per thread.
// Fragment mapping: tx in lane bits {0,1,4}, ty in {2,3}+warp -> conflict-free
// Bs reads (per-phase addresses 0/32/64/96B mod 128) and broadcast As reads.
__device__ __forceinline__ float gelu_f(float x)
{
    return 0.5f * x * (1.f + erff(x * 0.7071067811865476f));
}

template <int EPI>
__global__ void __launch_bounds__(128) gemm_kernel(const float* __restrict__ A,
                                                   const float* __restrict__ B,
                                                   const float* __restrict__ bias,
                                                   const float* __restrict__ R,
                                                   float* __restrict__ C,
                                                   int M, int N, int K)
{
    __shared__ __align__(16) float As[16][68];   // transposed: As[k][m]
    __shared__ __align__(16) float Bs[16][64];

    int tid = threadIdx.x;
    int lane = tid & 31, w = tid >> 5;
    int tx = (lane & 3) | ((lane >> 2) & 4);       // 0..7, lane bits {0,1,4}
    int ty = ((lane >> 2) & 3) | (w << 2);         // 0..15, lane bits {2,3}+warp
    int m0 = blockIdx.y * 64, n0 = blockIdx.x * 64;

    float acc[4][8];
#pragma unroll
    for (int i = 0; i < 4; i++)
#pragma unroll
        for (int j = 0; j < 8; j++) acc[i][j] = 0.f;

    for (int k0 = 0; k0 < K; k0 += 16) {
        // A tile 64x16 (256 float4), stored transposed
#pragma unroll
        for (int it = 0; it < 2; ++it) {
            int i = tid + it * 128;
            int r = i >> 2, c = i & 3;
            float4 v = *(const float4*)&A[(size_t)(m0 + r) * K + k0 + c * 4];
            As[c * 4 + 0][r] = v.x; As[c * 4 + 1][r] = v.y;
            As[c * 4 + 2][r] = v.z; As[c * 4 + 3][r] = v.w;
        }
        // B tile 16x64 (256 float4)
#pragma unroll
        for (int it = 0; it < 2; ++it) {
            int i = tid + it * 128;
            int r = i >> 4, c = i & 15;
            *(float4*)&Bs[r][c * 4] = *(const float4*)&B[(size_t)(k0 + r) * N + n0 + c * 4];
        }
        __syncthreads();
#pragma unroll
        for (int k = 0; k < 16; k++) {
            float4 a  = *(const float4*)&As[k][ty * 4];
            float4 b0 = *(const float4*)&Bs[k][tx * 8];
            float4 b1 = *(const float4*)&Bs[k][tx * 8 + 4];
            float av[4] = {a.x, a.y, a.z, a.w};
            float bv[8] = {b0.x, b0.y, b0.z, b0.w, b1.x, b1.y, b1.z, b1.w};
#pragma unroll
            for (int i = 0; i < 4; i++)
#pragma unroll
                for (int j = 0; j < 8; j++) acc[i][j] += av[i] * bv[j];
        }
        __syncthreads();
    }

    // epilogue
    float4 bias0 = *(const float4*)&bias[n0 + tx * 8];
    float4 bias1 = *(const float4*)&bias[n0 + tx * 8 + 4];
    float bb[8] = {bias0.x, bias0.y, bias0.z, bias0.w, bias1.x, bias1.y, bias1.z, bias1.w};
#pragma unroll
    for (int i = 0; i < 4; i++) {
        int m = m0 + ty * 4 + i;
        size_t off = (size_t)m * N + n0 + tx * 8;
        float vv[8];
#pragma unroll
        for (int j = 0; j < 8; j++) {
            float v = acc[i][j] + bb[j];
            if (EPI == 1) v = gelu_f(v);
            vv[j] = v;
        }
        if (EPI == 2) {
            float4 r0 = *(const float4*)&R[off];
            float4 r1 = *(const float4*)&R[off + 4];
            vv[0] += r0.x; vv[1] += r0.y; vv[2] += r0.z; vv[3] += r0.w;
            vv[4] += r1.x; vv[5] += r1.y; vv[6] += r1.z; vv[7] += r1.w;
        }
        *(float4*)&C[off]     = make_float4(vv[0], vv[1], vv[2], vv[3]);
        *(float4*)&C[off + 4] = make_float4(vv[4], vv[5], vv[6], vv[7]);
    }
}

// ---------------- flash attention v2: grid (S/64, NH, NB), 128 threads ----------------
// Q^T and K^T come pre-transposed (rope applied) from global: all smem stores are
// coalesced row-major float4 (no in-kernel transpose -> no 32-way conflicts).
// smem: Qt[64][68] | Kt[64][68] | Vs[64][68] | Ps[64][68]
#define AT_S 68
#define ATT_SMEM_FLOATS (4 * 64 * AT_S)

__global__ void __launch_bounds__(128) attn_kernel(const float* __restrict__ qtg,
                                                   const float* __restrict__ ktg,
                                                   const float* __restrict__ qkv,
                                                   float* __restrict__ out)
{
    extern __shared__ __align__(16) float smem[];
    float (*Qt)[AT_S] = (float(*)[AT_S])(smem);
    float (*Kt)[AT_S] = (float(*)[AT_S])(smem + 64 * AT_S);
    float (*Vs)[AT_S] = (float(*)[AT_S])(smem + 2 * 64 * AT_S);
    float (*Ps)[AT_S] = (float(*)[AT_S])(smem + 3 * 64 * AT_S);

    int tid = threadIdx.x;
    int lane = tid & 31, w = tid >> 5;
    int tx = (lane & 3) | ((lane >> 2) & 4);       // col-group, lane bits {0,1,4}
    int ty = ((lane >> 2) & 3) | (w << 2);         // row-group, lane bits {2,3}+warp
    int qt = blockIdx.x, h = blockIdx.y, b = blockIdx.z;
    int bh = b * NH + h;

    const float* Qg = qtg + (size_t)bh * HD * S_LEN + qt * 64;
    const float* Kg = ktg + (size_t)bh * HD * S_LEN;
    const float* Vg = qkv + (size_t)b * S_LEN * (3 * DIM) + 2 * DIM + h * HD;

    // load Qt tile: row d, 64 s-columns (coalesced gmem, conflict-free smem)
#pragma unroll
    for (int it = 0; it < 8; ++it) {
        int i = tid + it * 128;
        int d = i >> 4, c = i & 15;
        *(float4*)&Qt[d][c * 4] = *(const float4*)&Qg[(size_t)d * S_LEN + c * 4];
    }

    float m_r[4], l_r[4], accO[4][8];
#pragma unroll
    for (int i = 0; i < 4; i++) {
        m_r[i] = -1e30f; l_r[i] = 0.f;
#pragma unroll
        for (int j = 0; j < 8; j++) accO[i][j] = 0.f;
    }
    const float scale = 0.125f;   // 1/sqrt(64)

    for (int nt = 0; nt < S_LEN / 64; ++nt) {
        __syncthreads();   // previous PV reads of Kt/Vs/Ps done
        // load K^T tile (row d, s cols) and V tile (row token, d cols)
#pragma unroll
        for (int it = 0; it < 8; ++it) {
            int i = tid + it * 128;
            int r = i >> 4, c = i & 15;
            *(float4*)&Kt[r][c * 4] =
                *(const float4*)&Kg[(size_t)r * S_LEN + nt * 64 + c * 4];
            *(float4*)&Vs[r][c * 4] =
                *(const float4*)&Vg[(size_t)(nt * 64 + r) * (3 * DIM) + c * 4];
        }
        __syncthreads();

        // S = Q K^T (4x8 per thread): a = Qt[d][ty*4..] (broadcast pairs),
        // b = Kt[d][tx*8..] (phase addrs 0/32/64/96B mod 128 -> conflict-free)
        float s[4][8];
#pragma unroll
        for (int i = 0; i < 4; i++)
#pragma unroll
            for (int j = 0; j < 8; j++) s[i][j] = 0.f;
#pragma unroll 8
        for (int d = 0; d < 64; ++d) {
            float4 a  = *(const float4*)&Qt[d][ty * 4];
            float4 b0 = *(const float4*)&Kt[d][tx * 8];
            float4 b1 = *(const float4*)&Kt[d][tx * 8 + 4];
            float av[4] = {a.x, a.y, a.z, a.w};
            float bv[8] = {b0.x, b0.y, b0.z, b0.w, b1.x, b1.y, b1.z, b1.w};
#pragma unroll
            for (int i = 0; i < 4; i++)
#pragma unroll
                for (int j = 0; j < 8; j++) s[i][j] += av[i] * bv[j];
        }

        // online softmax update; row spans tx = lane bits {0,1,4} -> masks 1,2,16
#pragma unroll
        for (int i = 0; i < 4; i++) {
            float mt = -1e30f;
#pragma unroll
            for (int j = 0; j < 8; j++) { s[i][j] *= scale; mt = fmaxf(mt, s[i][j]); }
            mt = fmaxf(mt, __shfl_xor_sync(0xffffffffu, mt, 1));
            mt = fmaxf(mt, __shfl_xor_sync(0xffffffffu, mt, 2));
            mt = fmaxf(mt, __shfl_xor_sync(0xffffffffu, mt, 16));
            float mn = fmaxf(m_r[i], mt);
            float alpha = __expf(m_r[i] - mn);
            float rs = 0.f;
            float p[8];
#pragma unroll
            for (int j = 0; j < 8; j++) {
                p[j] = __expf(s[i][j] - mn);
                rs += p[j];
            }
            *(float4*)&Ps[ty * 4 + i][tx * 8]     = make_float4(p[0], p[1], p[2], p[3]);
            *(float4*)&Ps[ty * 4 + i][tx * 8 + 4] = make_float4(p[4], p[5], p[6], p[7]);
            rs += __shfl_xor_sync(0xffffffffu, rs, 1);
            rs += __shfl_xor_sync(0xffffffffu, rs, 2);
            rs += __shfl_xor_sync(0xffffffffu, rs, 16);
            l_r[i] = l_r[i] * alpha + rs;
            m_r[i] = mn;
#pragma unroll
            for (int j = 0; j < 8; j++) accO[i][j] *= alpha;
        }
        __syncthreads();   // Ps visible

        // O += P @ V : p scalars conflict-free (2 distinct + broadcast per phase)
#pragma unroll 8
        for (int j = 0; j < 64; ++j) {
            float p0 = Ps[ty * 4 + 0][j], p1 = Ps[ty * 4 + 1][j];
            float p2 = Ps[ty * 4 + 2][j], p3 = Ps[ty * 4 + 3][j];
            float4 v0 = *(const float4*)&Vs[j][tx * 8];
            float4 v1 = *(const float4*)&Vs[j][tx * 8 + 4];
            float vv[8] = {v0.x, v0.y, v0.z, v0.w, v1.x, v1.y, v1.z, v1.w};
#pragma unroll
            for (int c = 0; c < 8; c++) {
                accO[0][c] += p0 * vv[c]; accO[1][c] += p1 * vv[c];
                accO[2][c] += p2 * vv[c]; accO[3][c] += p3 * vv[c];
            }
        }
    }

    // write O / l to (b, s, h*HD + d) layout
#pragma unroll
    for (int i = 0; i < 4; i++) {
        float inv = 1.f / l_r[i];
        int row = b * S_LEN + qt * 64 + ty * 4 + i;
        size_t off = (size_t)row * DIM + h * HD + tx * 8;
        *(float4*)&out[off] = make_float4(accO[i][0] * inv, accO[i][1] * inv,
                                          accO[i][2] * inv, accO[i][3] * inv);
        *(float4*)&out[off + 4] = make_float4(accO[i][4] * inv, accO[i][5] * inv,
                                              accO[i][6] * inv, accO[i][7] * inv);
    }
}

// ---------------- launcher ----------------
extern "C" void kernel_launch(void* const* d_in, const int* in_sizes, int n_in,
                              void* d_out, int out_size)
{
    const float* x        = (const float*)d_in[0];
    const float* rope_cos = (const float*)d_in[1];
    const float* rope_sin = (const float*)d_in[2];
    const float* n1g      = (const float*)d_in[3];
    const float* n1b      = (const float*)d_in[4];
    const float* n2g      = (const float*)d_in[5];
    const float* n2b      = (const float*)d_in[6];
    const float* w_qkv    = (const float*)d_in[7];
    const float* b_qkv    = (const float*)d_in[8];
    const float* w_proj   = (const float*)d_in[9];
    const float* b_proj   = (const float*)d_in[10];
    const float* w_fc1    = (const float*)d_in[11];
    const float* b_fc1    = (const float*)d_in[12];
    const float* w_fc2    = (const float*)d_in[13];
    const float* b_fc2    = (const float*)d_in[14];
    float* out = (float*)d_out;

    float *ph, *pqkv, *pqt, *pkt, *patt, *px1, *pmid;
    cudaGetSymbolAddress((void**)&ph,   g_h);
    cudaGetSymbolAddress((void**)&pqkv, g_qkv);
    cudaGetSymbolAddress((void**)&pqt,  g_qt);
    cudaGetSymbolAddress((void**)&pkt,  g_kt);
    cudaGetSymbolAddress((void**)&patt, g_att);
    cudaGetSymbolAddress((void**)&px1,  g_x1);
    cudaGetSymbolAddress((void**)&pmid, g_mid);

    // opt-in dynamic smem for attention (~68 KB); idempotent, capture-safe
    cudaFuncSetAttribute(attn_kernel, cudaFuncAttributeMaxDynamicSharedMemorySize,
                         ATT_SMEM_FLOATS * (int)sizeof(float));

    // 1) LN1
    ln_kernel<<<TOK, 256>>>(x, n1g, n1b, ph);
    // 2) QKV GEMM + bias
    gemm_kernel<0><<<dim3(3 * DIM / 64, TOK / 64), 128>>>(ph, w_qkv, b_qkv, nullptr, pqkv,
                                                          TOK, 3 * DIM, DIM);
    // 3) fused RoPE + transpose of Q,K -> [bh][d][s]
    qk_rope_transpose<<<dim3(S_LEN / 32, NB * NH), 256>>>(pqkv, rope_cos, rope_sin,
                                                          pqt, pkt);
    // 4) attention
    attn_kernel<<<dim3(S_LEN / 64, NH, NB), 128, ATT_SMEM_FLOATS * sizeof(float)>>>(
        pqt, pkt, pqkv, patt);
    // 5) proj + bias + residual(x)
    gemm_kernel<2><<<dim3(DIM / 64, TOK / 64), 128>>>(patt, w_proj, b_proj, x, px1,
                                                      TOK, DIM, DIM);
    // 6) LN2
    ln_kernel<<<TOK, 256>>>(px1, n2g, n2b, ph);
    // 7) FC1 + bias + GELU
    gemm_kernel<1><<<dim3(4 * DIM / 64, TOK / 64), 128>>>(ph, w_fc1, b_fc1, nullptr, pmid,
                                                          TOK, 4 * DIM, DIM);
    // 8) FC2 + bias + residual(x1) -> out
    gemm_kernel<2><<<dim3(DIM / 64, TOK / 64), 128>>>(pmid, w_fc2, b_fc2, px1, out,
                                                      TOK, DIM, 4 * DIM);
}

// round 11
// speedup vs baseline: 1.6536x; 1.0493x over previous
#include <cuda_runtime.h>
#include <math.h>

// ---------------- problem constants ----------------
#define NB    4
#define S_LEN 2048
#define DIM   512
#define NH    8
#define HD    64
#define TOK   (NB * S_LEN)          // 8192

typedef unsigned long long ull;

// ---- packed f32x2 helpers (FFMA2 path: only reachable via PTX) ----
__device__ __forceinline__ ull pk2(float a, float b)
{
    ull r; asm("mov.b64 %0, {%1, %2};" : "=l"(r) : "f"(a), "f"(b)); return r;
}
__device__ __forceinline__ ull pkdup(float a) { return pk2(a, a); }
__device__ __forceinline__ float2 unpk(ull v)
{
    float2 r; asm("mov.b64 {%0, %1}, %2;" : "=f"(r.x), "=f"(r.y) : "l"(v)); return r;
}
__device__ __forceinline__ void fma2(ull& d, ull a, ull b)
{
    asm("fma.rn.f32x2 %0, %1, %2, %0;" : "+l"(d) : "l"(a), "l"(b));
}
__device__ __forceinline__ void mul2(ull& d, ull a)
{
    asm("mul.rn.f32x2 %0, %0, %1;" : "+l"(d) : "l"(a));
}

// ---------------- scratch (no allocations allowed) ----------------
__device__ float g_h[TOK * DIM];
__device__ float g_qkv[TOK * 3 * DIM];
__device__ float g_qt[NB * NH * HD * S_LEN];   // Q^T per (b,h): [d][s], rope applied
__device__ float g_kt[NB * NH * HD * S_LEN];   // K^T per (b,h): [d][s], rope applied
__device__ float g_att[TOK * DIM];
__device__ float g_x1[TOK * DIM];
__device__ float g_mid[TOK * 4 * DIM];

// ---------------- LayerNorm ----------------
__global__ void __launch_bounds__(256) ln_kernel(const float* __restrict__ x,
                                                 const float* __restrict__ g,
                                                 const float* __restrict__ b,
                                                 float* __restrict__ out)
{
    int row = blockIdx.x;
    int t = threadIdx.x;
    const float2* xr = (const float2*)(x + (size_t)row * DIM);
    float2 v = xr[t];
    float s = v.x + v.y;
    float ss = v.x * v.x + v.y * v.y;
#pragma unroll
    for (int m = 16; m; m >>= 1) {
        s  += __shfl_xor_sync(0xffffffffu, s, m);
        ss += __shfl_xor_sync(0xffffffffu, ss, m);
    }
    __shared__ float sh[16];
    int w = t >> 5;
    if ((t & 31) == 0) { sh[w] = s; sh[8 + w] = ss; }
    __syncthreads();
    s = 0.f; ss = 0.f;
#pragma unroll
    for (int i = 0; i < 8; i++) { s += sh[i]; ss += sh[8 + i]; }
    float mu  = s * (1.f / DIM);
    float var = ss * (1.f / DIM) - mu * mu;
    float inv = rsqrtf(var + 1e-5f);
    float2 gg = ((const float2*)g)[t];
    float2 bb = ((const float2*)b)[t];
    float2 o;
    o.x = (v.x - mu) * inv * gg.x + bb.x;
    o.y = (v.y - mu) * inv * gg.y + bb.y;
    ((float2*)(out + (size_t)row * DIM))[t] = o;
}

// ---------------- fused RoPE + transpose of Q,K into [bh][d][s] ----------------
__global__ void __launch_bounds__(256) qk_rope_transpose(const float* __restrict__ qkv,
                                                         const float* __restrict__ cb,
                                                         const float* __restrict__ sb,
                                                         float* __restrict__ qt,
                                                         float* __restrict__ kt)
{
    __shared__ float tq[32][65], tk[32][65], tc[32][65], tss[32][65];
    int s0 = blockIdx.x * 32;
    int bh = blockIdx.y;
    int b = bh >> 3, h = bh & 7;
    int tid = threadIdx.x;
    int d = tid & 63, sl = tid >> 6;
#pragma unroll
    for (int it = 0; it < 8; it++) {
        int s = sl + it * 4;
        size_t ro = ((size_t)(b * S_LEN + s0 + s)) * (3 * DIM) + h * HD + d;
        tq[s][d]  = qkv[ro];
        tk[s][d]  = qkv[ro + DIM];
        tc[s][d]  = cb[(s0 + s) * HD + d];
        tss[s][d] = sb[(s0 + s) * HD + d];
    }
    __syncthreads();
    int sw = tid & 31, dw = tid >> 5;
#pragma unroll
    for (int it = 0; it < 8; it++) {
        int dd = dw + it * 8;
        float c = tc[sw][dd], sn = tss[sw][dd];
        float q0 = tq[sw][dd], q1 = tq[sw][dd ^ 32];
        float k0 = tk[sw][dd], k1 = tk[sw][dd ^ 32];
        float rq = (dd < 32) ? (q0 * c - q1 * sn) : (q0 * c + q1 * sn);
        float rk = (dd < 32) ? (k0 * c - k1 * sn) : (k0 * c + k1 * sn);
        size_t wo = ((size_t)bh * HD + dd) * S_LEN + s0 + sw;
        qt[wo] = rq;
        kt[wo] = rk;
    }
}

// ---------------- 128x128x16 GEMM, 256 threads, 8x8/thread, FFMA2 ----------------
__device__ __forceinline__ float gelu_f(float x)
{
    return 0.5f * x * (1.f + erff(x * 0.7071067811865476f));
}

template <int EPI>
__global__ void __launch_bounds__(256) gemm_kernel(const float* __restrict__ A,
                                                   const float* __restrict__ B,
                                                   const float* __restrict__ bias,
                                                   const float* __restrict__ R,
                                                   float* __restrict__ C,
                                                   int M, int N, int K)
{
    __shared__ __align__(16) float As[16][132];   // transposed: As[k][m]
    __shared__ __align__(16) float Bs[16][128];

    int tid = threadIdx.x;
    int lane = tid & 31, w = tid >> 5;             // w: 0..7
    int tx = (lane & 3) | ((w & 3) << 2);          // 0..15 col-group
    int ty = (lane >> 2) | ((w >> 2) << 3);        // 0..15 row-group
    int m0 = blockIdx.y * 128, n0 = blockIdx.x * 128;

    ull acc2[8][4];
#pragma unroll
    for (int i = 0; i < 8; i++)
#pragma unroll
        for (int j = 0; j < 4; j++) acc2[i][j] = 0ull;

    for (int k0 = 0; k0 < K; k0 += 16) {
        // A tile 128x16 -> transposed As[k][m]
#pragma unroll
        for (int it = 0; it < 2; ++it) {
            int i = tid + it * 256;
            int r = i >> 2, c = i & 3;
            float4 v = *(const float4*)&A[(size_t)(m0 + r) * K + k0 + c * 4];
            As[c * 4 + 0][r] = v.x; As[c * 4 + 1][r] = v.y;
            As[c * 4 + 2][r] = v.z; As[c * 4 + 3][r] = v.w;
        }
        // B tile 16x128
#pragma unroll
        for (int it = 0; it < 2; ++it) {
            int i = tid + it * 256;
            int r = i >> 5, c = i & 31;
            *(float4*)&Bs[r][c * 4] = *(const float4*)&B[(size_t)(k0 + r) * N + n0 + c * 4];
        }
        __syncthreads();
#pragma unroll
        for (int k = 0; k < 16; k++) {
            float4 a0 = *(const float4*)&As[k][ty * 8];
            float4 a1 = *(const float4*)&As[k][ty * 8 + 4];
            ulonglong2 b0 = *(const ulonglong2*)&Bs[k][tx * 8];
            ulonglong2 b1 = *(const ulonglong2*)&Bs[k][tx * 8 + 4];
            ull bv[4] = {b0.x, b0.y, b1.x, b1.y};
            ull ad[8] = {pkdup(a0.x), pkdup(a0.y), pkdup(a0.z), pkdup(a0.w),
                         pkdup(a1.x), pkdup(a1.y), pkdup(a1.z), pkdup(a1.w)};
#pragma unroll
            for (int i = 0; i < 8; i++)
#pragma unroll
                for (int j = 0; j < 4; j++) fma2(acc2[i][j], ad[i], bv[j]);
        }
        __syncthreads();
    }

    // epilogue
    float4 bias0 = *(const float4*)&bias[n0 + tx * 8];
    float4 bias1 = *(const float4*)&bias[n0 + tx * 8 + 4];
    float bb[8] = {bias0.x, bias0.y, bias0.z, bias0.w, bias1.x, bias1.y, bias1.z, bias1.w};
#pragma unroll
    for (int i = 0; i < 8; i++) {
        int m = m0 + ty * 8 + i;
        size_t off = (size_t)m * N + n0 + tx * 8;
        float2 u0 = unpk(acc2[i][0]), u1 = unpk(acc2[i][1]);
        float2 u2 = unpk(acc2[i][2]), u3 = unpk(acc2[i][3]);
        float vv[8] = {u0.x, u0.y, u1.x, u1.y, u2.x, u2.y, u3.x, u3.y};
#pragma unroll
        for (int j = 0; j < 8; j++) {
            float v = vv[j] + bb[j];
            if (EPI == 1) v = gelu_f(v);
            vv[j] = v;
        }
        if (EPI == 2) {
            float4 r0 = *(const float4*)&R[off];
            float4 r1 = *(const float4*)&R[off + 4];
            vv[0] += r0.x; vv[1] += r0.y; vv[2] += r0.z; vv[3] += r0.w;
            vv[4] += r1.x; vv[5] += r1.y; vv[6] += r1.z; vv[7] += r1.w;
        }
        *(float4*)&C[off]     = make_float4(vv[0], vv[1], vv[2], vv[3]);
        *(float4*)&C[off + 4] = make_float4(vv[4], vv[5], vv[6], vv[7]);
    }
}

// ---------------- flash attention: 128 q-rows/CTA, 8x8/thread, FFMA2 ----------------
// grid (S/128, NH, NB), 128 threads
// smem: Qt[64][132] | Kt[64][68] | Vs[64][68] | Ps[128][68]
#define AQ 132
#define AK 68
#define ATT_SMEM_FLOATS (64 * AQ + 64 * AK + 64 * AK + 128 * AK)

__global__ void __launch_bounds__(128) attn_kernel(const float* __restrict__ qtg,
                                                   const float* __restrict__ ktg,
                                                   const float* __restrict__ qkv,
                                                   float* __restrict__ out)
{
    extern __shared__ __align__(16) float smem[];
    float (*Qt)[AQ] = (float(*)[AQ])(smem);
    float (*Kt)[AK] = (float(*)[AK])(smem + 64 * AQ);
    float (*Vs)[AK] = (float(*)[AK])(smem + 64 * AQ + 64 * AK);
    float (*Ps)[AK] = (float(*)[AK])(smem + 64 * AQ + 2 * 64 * AK);

    int tid = threadIdx.x;
    int lane = tid & 31, w = tid >> 5;
    int tx = (lane & 3) | ((lane >> 2) & 4);       // 0..7 key-col group (lane bits {0,1,4})
    int ty = ((lane >> 2) & 3) | (w << 2);         // 0..15 q-row group
    int qt = blockIdx.x, h = blockIdx.y, b = blockIdx.z;
    int bh = b * NH + h;

    const float* Qg = qtg + (size_t)bh * HD * S_LEN + qt * 128;
    const float* Kg = ktg + (size_t)bh * HD * S_LEN;
    const float* Vg = qkv + (size_t)b * S_LEN * (3 * DIM) + 2 * DIM + h * HD;

    // load Q^T tile: 64 d-rows x 128 s-cols
#pragma unroll
    for (int it = 0; it < 16; ++it) {
        int i = tid + it * 128;
        int d = i >> 5, c = i & 31;
        *(float4*)&Qt[d][c * 4] = *(const float4*)&Qg[(size_t)d * S_LEN + c * 4];
    }

    float m_r[8], l_r[8];
    ull accO2[8][4];
#pragma unroll
    for (int i = 0; i < 8; i++) {
        m_r[i] = -1e30f; l_r[i] = 0.f;
#pragma unroll
        for (int j = 0; j < 4; j++) accO2[i][j] = 0ull;
    }
    const float scale = 0.125f;   // 1/sqrt(64)

    for (int nt = 0; nt < S_LEN / 64; ++nt) {
        __syncthreads();
#pragma unroll
        for (int it = 0; it < 8; ++it) {
            int i = tid + it * 128;
            int r = i >> 4, c = i & 15;
            *(float4*)&Kt[r][c * 4] =
                *(const float4*)&Kg[(size_t)r * S_LEN + nt * 64 + c * 4];
            *(float4*)&Vs[r][c * 4] =
                *(const float4*)&Vg[(size_t)(nt * 64 + r) * (3 * DIM) + c * 4];
        }
        __syncthreads();

        // S = Q^T(K^T): 8 q-rows x 8 keys per thread, packed over key pairs
        ull s2[8][4];
#pragma unroll
        for (int i = 0; i < 8; i++)
#pragma unroll
            for (int j = 0; j < 4; j++) s2[i][j] = 0ull;
#pragma unroll 4
        for (int d = 0; d < 64; ++d) {
            float4 a0 = *(const float4*)&Qt[d][ty * 8];
            float4 a1 = *(const float4*)&Qt[d][ty * 8 + 4];
            ulonglong2 b0 = *(const ulonglong2*)&Kt[d][tx * 8];
            ulonglong2 b1 = *(const ulonglong2*)&Kt[d][tx * 8 + 4];
            ull bv[4] = {b0.x, b0.y, b1.x, b1.y};
            ull ad[8] = {pkdup(a0.x), pkdup(a0.y), pkdup(a0.z), pkdup(a0.w),
                         pkdup(a1.x), pkdup(a1.y), pkdup(a1.z), pkdup(a1.w)};
#pragma unroll
            for (int i = 0; i < 8; i++)
#pragma unroll
                for (int j = 0; j < 4; j++) fma2(s2[i][j], ad[i], bv[j]);
        }

        // online softmax (row spans tx lanes -> shuffle masks 1,2,16)
#pragma unroll
        for (int i = 0; i < 8; i++) {
            float2 t0 = unpk(s2[i][0]), t1 = unpk(s2[i][1]);
            float2 t2 = unpk(s2[i][2]), t3 = unpk(s2[i][3]);
            float sv[8] = {t0.x, t0.y, t1.x, t1.y, t2.x, t2.y, t3.x, t3.y};
            float mt = -1e30f;
#pragma unroll
            for (int j = 0; j < 8; j++) { sv[j] *= scale; mt = fmaxf(mt, sv[j]); }
            mt = fmaxf(mt, __shfl_xor_sync(0xffffffffu, mt, 1));
            mt = fmaxf(mt, __shfl_xor_sync(0xffffffffu, mt, 2));
            mt = fmaxf(mt, __shfl_xor_sync(0xffffffffu, mt, 16));
            float mn = fmaxf(m_r[i], mt);
            float alpha = __expf(m_r[i] - mn);
            float rs = 0.f;
            float p[8];
#pragma unroll
            for (int j = 0; j < 8; j++) { p[j] = __expf(sv[j] - mn); rs += p[j]; }
            *(float4*)&Ps[ty * 8 + i][tx * 8]     = make_float4(p[0], p[1], p[2], p[3]);
            *(float4*)&Ps[ty * 8 + i][tx * 8 + 4] = make_float4(p[4], p[5], p[6], p[7]);
            rs += __shfl_xor_sync(0xffffffffu, rs, 1);
            rs += __shfl_xor_sync(0xffffffffu, rs, 2);
            rs += __shfl_xor_sync(0xffffffffu, rs, 16);
            l_r[i] = l_r[i] * alpha + rs;
            m_r[i] = mn;
            ull al2 = pkdup(alpha);
#pragma unroll
            for (int j = 0; j < 4; j++) mul2(accO2[i][j], al2);
        }
        __syncthreads();   // Ps visible

        // O += P @ V
#pragma unroll 4
        for (int j = 0; j < 64; ++j) {
            ulonglong2 v0 = *(const ulonglong2*)&Vs[j][tx * 8];
            ulonglong2 v1 = *(const ulonglong2*)&Vs[j][tx * 8 + 4];
            ull vb[4] = {v0.x, v0.y, v1.x, v1.y};
#pragma unroll
            for (int i = 0; i < 8; i++) {
                ull pd = pkdup(Ps[ty * 8 + i][j]);
#pragma unroll
                for (int c = 0; c < 4; c++) fma2(accO2[i][c], pd, vb[c]);
            }
        }
    }

    // write O (b, s, h*HD + d)
#pragma unroll
    for (int i = 0; i < 8; i++) {
        float inv = 1.f / l_r[i];
        int row = b * S_LEN + qt * 128 + ty * 8 + i;
        size_t off = (size_t)row * DIM + h * HD + tx * 8;
        float2 u0 = unpk(accO2[i][0]), u1 = unpk(accO2[i][1]);
        float2 u2 = unpk(accO2[i][2]), u3 = unpk(accO2[i][3]);
        *(float4*)&out[off]     = make_float4(u0.x * inv, u0.y * inv, u1.x * inv, u1.y * inv);
        *(float4*)&out[off + 4] = make_float4(u2.x * inv, u2.y * inv, u3.x * inv, u3.y * inv);
    }
}

// ---------------- launcher ----------------
extern "C" void kernel_launch(void* const* d_in, const int* in_sizes, int n_in,
                              void* d_out, int out_size)
{
    const float* x        = (const float*)d_in[0];
    const float* rope_cos = (const float*)d_in[1];
    const float* rope_sin = (const float*)d_in[2];
    const float* n1g      = (const float*)d_in[3];
    const float* n1b      = (const float*)d_in[4];
    const float* n2g      = (const float*)d_in[5];
    const float* n2b      = (const float*)d_in[6];
    const float* w_qkv    = (const float*)d_in[7];
    const float* b_qkv    = (const float*)d_in[8];
    const float* w_proj   = (const float*)d_in[9];
    const float* b_proj   = (const float*)d_in[10];
    const float* w_fc1    = (const float*)d_in[11];
    const float* b_fc1    = (const float*)d_in[12];
    const float* w_fc2    = (const float*)d_in[13];
    const float* b_fc2    = (const float*)d_in[14];
    float* out = (float*)d_out;

    float *ph, *pqkv, *pqt, *pkt, *patt, *px1, *pmid;
    cudaGetSymbolAddress((void**)&ph,   g_h);
    cudaGetSymbolAddress((void**)&pqkv, g_qkv);
    cudaGetSymbolAddress((void**)&pqt,  g_qt);
    cudaGetSymbolAddress((void**)&pkt,  g_kt);
    cudaGetSymbolAddress((void**)&patt, g_att);
    cudaGetSymbolAddress((void**)&px1,  g_x1);
    cudaGetSymbolAddress((void**)&pmid, g_mid);

    cudaFuncSetAttribute(attn_kernel, cudaFuncAttributeMaxDynamicSharedMemorySize,
                         ATT_SMEM_FLOATS * (int)sizeof(float));

    // 1) LN1
    ln_kernel<<<TOK, 256>>>(x, n1g, n1b, ph);
    // 2) QKV GEMM + bias
    gemm_kernel<0><<<dim3(3 * DIM / 128, TOK / 128), 256>>>(ph, w_qkv, b_qkv, nullptr, pqkv,
                                                            TOK, 3 * DIM, DIM);
    // 3) fused RoPE + transpose of Q,K -> [bh][d][s]
    qk_rope_transpose<<<dim3(S_LEN / 32, NB * NH), 256>>>(pqkv, rope_cos, rope_sin,
                                                          pqt, pkt);
    // 4) attention
    attn_kernel<<<dim3(S_LEN / 128, NH, NB), 128, ATT_SMEM_FLOATS * sizeof(float)>>>(
        pqt, pkt, pqkv, patt);
    // 5) proj + bias + residual(x)
    gemm_kernel<2><<<dim3(DIM / 128, TOK / 128), 256>>>(patt, w_proj, b_proj, x, px1,
                                                        TOK, DIM, DIM);
    // 6) LN2
    ln_kernel<<<TOK, 256>>>(px1, n2g, n2b, ph);
    // 7) FC1 + bias + GELU
    gemm_kernel<1><<<dim3(4 * DIM / 128, TOK / 128), 256>>>(ph, w_fc1, b_fc1, nullptr, pmid,
                                                            TOK, 4 * DIM, DIM);
    // 8) FC2 + bias + residual(x1) -> out
    gemm_kernel<2><<<dim3(DIM / 128, TOK / 128), 256>>>(pmid, w_fc2, b_fc2, px1, out,
                                                        TOK, DIM, 4 * DIM);
}

// round 12
// speedup vs baseline: 1.7831x; 1.0783x over previous
#include <cuda_runtime.h>
#include <math.h>

// ---------------- problem constants ----------------
#define NB    4
#define S_LEN 2048
#define DIM   512
#define NH    8
#define HD    64
#define TOK   (NB * S_LEN)          // 8192

typedef unsigned long long ull;

// ---- packed f32x2 helpers (FFMA2 path: only reachable via PTX) ----
__device__ __forceinline__ ull pk2(float a, float b)
{
    ull r; asm("mov.b64 %0, {%1, %2};" : "=l"(r) : "f"(a), "f"(b)); return r;
}
__device__ __forceinline__ ull pkdup(float a) { return pk2(a, a); }
__device__ __forceinline__ float2 unpk(ull v)
{
    float2 r; asm("mov.b64 {%0, %1}, %2;" : "=f"(r.x), "=f"(r.y) : "l"(v)); return r;
}
__device__ __forceinline__ void fma2(ull& d, ull a, ull b)
{
    asm("fma.rn.f32x2 %0, %1, %2, %0;" : "+l"(d) : "l"(a), "l"(b));
}
__device__ __forceinline__ void mul2(ull& d, ull a)
{
    asm("mul.rn.f32x2 %0, %0, %1;" : "+l"(d) : "l"(a));
}

// ---------------- scratch (no allocations allowed) ----------------
__device__ float g_h[TOK * DIM];
__device__ float g_qkv[TOK * 3 * DIM];
__device__ float g_qt[NB * NH * HD * S_LEN];   // Q^T per (b,h): [d][s], rope applied
__device__ float g_kt[NB * NH * HD * S_LEN];   // K^T per (b,h): [d][s], rope applied
__device__ float g_att[TOK * DIM];
__device__ float g_x1[TOK * DIM];
__device__ float g_mid[TOK * 4 * DIM];

// ---------------- LayerNorm ----------------
__global__ void __launch_bounds__(256) ln_kernel(const float* __restrict__ x,
                                                 const float* __restrict__ g,
                                                 const float* __restrict__ b,
                                                 float* __restrict__ out)
{
    int row = blockIdx.x;
    int t = threadIdx.x;
    const float2* xr = (const float2*)(x + (size_t)row * DIM);
    float2 v = xr[t];
    float s = v.x + v.y;
    float ss = v.x * v.x + v.y * v.y;
#pragma unroll
    for (int m = 16; m; m >>= 1) {
        s  += __shfl_xor_sync(0xffffffffu, s, m);
        ss += __shfl_xor_sync(0xffffffffu, ss, m);
    }
    __shared__ float sh[16];
    int w = t >> 5;
    if ((t & 31) == 0) { sh[w] = s; sh[8 + w] = ss; }
    __syncthreads();
    s = 0.f; ss = 0.f;
#pragma unroll
    for (int i = 0; i < 8; i++) { s += sh[i]; ss += sh[8 + i]; }
    float mu  = s * (1.f / DIM);
    float var = ss * (1.f / DIM) - mu * mu;
    float inv = rsqrtf(var + 1e-5f);
    float2 gg = ((const float2*)g)[t];
    float2 bb = ((const float2*)b)[t];
    float2 o;
    o.x = (v.x - mu) * inv * gg.x + bb.x;
    o.y = (v.y - mu) * inv * gg.y + bb.y;
    ((float2*)(out + (size_t)row * DIM))[t] = o;
}

// ---------------- fused RoPE + transpose of Q,K into [bh][d][s] ----------------
__global__ void __launch_bounds__(256) qk_rope_transpose(const float* __restrict__ qkv,
                                                         const float* __restrict__ cb,
                                                         const float* __restrict__ sb,
                                                         float* __restrict__ qt,
                                                         float* __restrict__ kt)
{
    __shared__ float tq[32][65], tk[32][65], tc[32][65], tss[32][65];
    int s0 = blockIdx.x * 32;
    int bh = blockIdx.y;
    int b = bh >> 3, h = bh & 7;
    int tid = threadIdx.x;
    int d = tid & 63, sl = tid >> 6;
#pragma unroll
    for (int it = 0; it < 8; it++) {
        int s = sl + it * 4;
        size_t ro = ((size_t)(b * S_LEN + s0 + s)) * (3 * DIM) + h * HD + d;
        tq[s][d]  = qkv[ro];
        tk[s][d]  = qkv[ro + DIM];
        tc[s][d]  = cb[(s0 + s) * HD + d];
        tss[s][d] = sb[(s0 + s) * HD + d];
    }
    __syncthreads();
    int sw = tid & 31, dw = tid >> 5;
#pragma unroll
    for (int it = 0; it < 8; it++) {
        int dd = dw + it * 8;
        float c = tc[sw][dd], sn = tss[sw][dd];
        float q0 = tq[sw][dd], q1 = tq[sw][dd ^ 32];
        float k0 = tk[sw][dd], k1 = tk[sw][dd ^ 32];
        float rq = (dd < 32) ? (q0 * c - q1 * sn) : (q0 * c + q1 * sn);
        float rk = (dd < 32) ? (k0 * c - k1 * sn) : (k0 * c + k1 * sn);
        size_t wo = ((size_t)bh * HD + dd) * S_LEN + s0 + sw;
        qt[wo] = rq;
        kt[wo] = rk;
    }
}

// ---------------- 128x128x16 GEMM, 256 threads, 8x8/thread, FFMA2 ----------------
__device__ __forceinline__ float gelu_f(float x)
{
    return 0.5f * x * (1.f + erff(x * 0.7071067811865476f));
}

template <int EPI>
__global__ void __launch_bounds__(256) gemm_kernel(const float* __restrict__ A,
                                                   const float* __restrict__ B,
                                                   const float* __restrict__ bias,
                                                   const float* __restrict__ R,
                                                   float* __restrict__ C,
                                                   int M, int N, int K)
{
    __shared__ __align__(16) float As[16][132];   // transposed: As[k][m]
    __shared__ __align__(16) float Bs[16][128];

    int tid = threadIdx.x;
    int lane = tid & 31, w = tid >> 5;             // w: 0..7
    int tx = (lane & 3) | ((w & 3) << 2);          // 0..15 col-group
    int ty = (lane >> 2) | ((w >> 2) << 3);        // 0..15 row-group
    int m0 = blockIdx.y * 128, n0 = blockIdx.x * 128;

    ull acc2[8][4];
#pragma unroll
    for (int i = 0; i < 8; i++)
#pragma unroll
        for (int j = 0; j < 4; j++) acc2[i][j] = 0ull;

    for (int k0 = 0; k0 < K; k0 += 16) {
        // A tile 128x16 -> transposed As[k][m]
#pragma unroll
        for (int it = 0; it < 2; ++it) {
            int i = tid + it * 256;
            int r = i >> 2, c = i & 3;
            float4 v = *(const float4*)&A[(size_t)(m0 + r) * K + k0 + c * 4];
            As[c * 4 + 0][r] = v.x; As[c * 4 + 1][r] = v.y;
            As[c * 4 + 2][r] = v.z; As[c * 4 + 3][r] = v.w;
        }
        // B tile 16x128
#pragma unroll
        for (int it = 0; it < 2; ++it) {
            int i = tid + it * 256;
            int r = i >> 5, c = i & 31;
            *(float4*)&Bs[r][c * 4] = *(const float4*)&B[(size_t)(k0 + r) * N + n0 + c * 4];
        }
        __syncthreads();
#pragma unroll
        for (int k = 0; k < 16; k++) {
            float4 a0 = *(const float4*)&As[k][ty * 8];
            float4 a1 = *(const float4*)&As[k][ty * 8 + 4];
            ulonglong2 b0 = *(const ulonglong2*)&Bs[k][tx * 8];
            ulonglong2 b1 = *(const ulonglong2*)&Bs[k][tx * 8 + 4];
            ull bv[4] = {b0.x, b0.y, b1.x, b1.y};
            ull ad[8] = {pkdup(a0.x), pkdup(a0.y), pkdup(a0.z), pkdup(a0.w),
                         pkdup(a1.x), pkdup(a1.y), pkdup(a1.z), pkdup(a1.w)};
#pragma unroll
            for (int i = 0; i < 8; i++)
#pragma unroll
                for (int j = 0; j < 4; j++) fma2(acc2[i][j], ad[i], bv[j]);
        }
        __syncthreads();
    }

    // epilogue
    float4 bias0 = *(const float4*)&bias[n0 + tx * 8];
    float4 bias1 = *(const float4*)&bias[n0 + tx * 8 + 4];
    float bb[8] = {bias0.x, bias0.y, bias0.z, bias0.w, bias1.x, bias1.y, bias1.z, bias1.w};
#pragma unroll
    for (int i = 0; i < 8; i++) {
        int m = m0 + ty * 8 + i;
        size_t off = (size_t)m * N + n0 + tx * 8;
        float2 u0 = unpk(acc2[i][0]), u1 = unpk(acc2[i][1]);
        float2 u2 = unpk(acc2[i][2]), u3 = unpk(acc2[i][3]);
        float vv[8] = {u0.x, u0.y, u1.x, u1.y, u2.x, u2.y, u3.x, u3.y};
#pragma unroll
        for (int j = 0; j < 8; j++) {
            float v = vv[j] + bb[j];
            if (EPI == 1) v = gelu_f(v);
            vv[j] = v;
        }
        if (EPI == 2) {
            float4 r0 = *(const float4*)&R[off];
            float4 r1 = *(const float4*)&R[off + 4];
            vv[0] += r0.x; vv[1] += r0.y; vv[2] += r0.z; vv[3] += r0.w;
            vv[4] += r1.x; vv[5] += r1.y; vv[6] += r1.z; vv[7] += r1.w;
        }
        *(float4*)&C[off]     = make_float4(vv[0], vv[1], vv[2], vv[3]);
        *(float4*)&C[off + 4] = make_float4(vv[4], vv[5], vv[6], vv[7]);
    }
}

// ---------------- flash attention: 128 q-rows/CTA, 256 threads, 4x8/thread ----------------
// grid (S/128, NH, NB). smem: Qt[64][132] | Kt[64][68] | Vs[64][68] | Ps[128][68]
#define AQ 132
#define AK 68
#define ATT_SMEM_FLOATS (64 * AQ + 64 * AK + 64 * AK + 128 * AK)

__global__ void __launch_bounds__(256) attn_kernel(const float* __restrict__ qtg,
                                                   const float* __restrict__ ktg,
                                                   const float* __restrict__ qkv,
                                                   float* __restrict__ out)
{
    extern __shared__ __align__(16) float smem[];
    float (*Qt)[AQ] = (float(*)[AQ])(smem);
    float (*Kt)[AK] = (float(*)[AK])(smem + 64 * AQ);
    float (*Vs)[AK] = (float(*)[AK])(smem + 64 * AQ + 64 * AK);
    float (*Ps)[AK] = (float(*)[AK])(smem + 64 * AQ + 2 * 64 * AK);

    int tid = threadIdx.x;
    int lane = tid & 31, w = tid >> 5;             // w: 0..7
    int tx = (lane & 3) | ((lane >> 2) & 4);       // 0..7 key-col group (lane bits {0,1,4})
    int ty = ((lane >> 2) & 3) | (w << 2);         // 0..31 q-row group
    int qt = blockIdx.x, h = blockIdx.y, b = blockIdx.z;
    int bh = b * NH + h;

    const float* Qg = qtg + (size_t)bh * HD * S_LEN + qt * 128;
    const float* Kg = ktg + (size_t)bh * HD * S_LEN;
    const float* Vg = qkv + (size_t)b * S_LEN * (3 * DIM) + 2 * DIM + h * HD;

    // load Q^T tile: 64 d-rows x 128 s-cols (2048 float4 / 256 thr = 8 iters)
#pragma unroll
    for (int it = 0; it < 8; ++it) {
        int i = tid + it * 256;
        int d = i >> 5, c = i & 31;
        *(float4*)&Qt[d][c * 4] = *(const float4*)&Qg[(size_t)d * S_LEN + c * 4];
    }

    float m_r[4], l_r[4];
    ull accO2[4][4];
#pragma unroll
    for (int i = 0; i < 4; i++) {
        m_r[i] = -1e30f; l_r[i] = 0.f;
#pragma unroll
        for (int j = 0; j < 4; j++) accO2[i][j] = 0ull;
    }
    const float scale = 0.125f;   // 1/sqrt(64)

    for (int nt = 0; nt < S_LEN / 64; ++nt) {
        __syncthreads();
        // K^T tile (64 d x 64 s) + V tile (64 tok x 64 d): 1024 f4 each / 256 thr
#pragma unroll
        for (int it = 0; it < 4; ++it) {
            int i = tid + it * 256;
            int r = i >> 4, c = i & 15;
            *(float4*)&Kt[r][c * 4] =
                *(const float4*)&Kg[(size_t)r * S_LEN + nt * 64 + c * 4];
            *(float4*)&Vs[r][c * 4] =
                *(const float4*)&Vg[(size_t)(nt * 64 + r) * (3 * DIM) + c * 4];
        }
        __syncthreads();

        // S = Q^T(K^T): 4 q-rows x 8 keys per thread, packed over key pairs
        ull s2[4][4];
#pragma unroll
        for (int i = 0; i < 4; i++)
#pragma unroll
            for (int j = 0; j < 4; j++) s2[i][j] = 0ull;
#pragma unroll 8
        for (int d = 0; d < 64; ++d) {
            float4 a = *(const float4*)&Qt[d][ty * 4];
            ulonglong2 b0 = *(const ulonglong2*)&Kt[d][tx * 8];
            ulonglong2 b1 = *(const ulonglong2*)&Kt[d][tx * 8 + 4];
            ull bv[4] = {b0.x, b0.y, b1.x, b1.y};
            ull ad[4] = {pkdup(a.x), pkdup(a.y), pkdup(a.z), pkdup(a.w)};
#pragma unroll
            for (int i = 0; i < 4; i++)
#pragma unroll
                for (int j = 0; j < 4; j++) fma2(s2[i][j], ad[i], bv[j]);
        }

        // online softmax (row spans tx lanes -> shuffle masks 1,2,16)
#pragma unroll
        for (int i = 0; i < 4; i++) {
            float2 t0 = unpk(s2[i][0]), t1 = unpk(s2[i][1]);
            float2 t2 = unpk(s2[i][2]), t3 = unpk(s2[i][3]);
            float sv[8] = {t0.x, t0.y, t1.x, t1.y, t2.x, t2.y, t3.x, t3.y};
            float mt = -1e30f;
#pragma unroll
            for (int j = 0; j < 8; j++) { sv[j] *= scale; mt = fmaxf(mt, sv[j]); }
            mt = fmaxf(mt, __shfl_xor_sync(0xffffffffu, mt, 1));
            mt = fmaxf(mt, __shfl_xor_sync(0xffffffffu, mt, 2));
            mt = fmaxf(mt, __shfl_xor_sync(0xffffffffu, mt, 16));
            float mn = fmaxf(m_r[i], mt);
            float alpha = __expf(m_r[i] - mn);
            float rs = 0.f;
            float p[8];
#pragma unroll
            for (int j = 0; j < 8; j++) { p[j] = __expf(sv[j] - mn); rs += p[j]; }
            *(float4*)&Ps[ty * 4 + i][tx * 8]     = make_float4(p[0], p[1], p[2], p[3]);
            *(float4*)&Ps[ty * 4 + i][tx * 8 + 4] = make_float4(p[4], p[5], p[6], p[7]);
            rs += __shfl_xor_sync(0xffffffffu, rs, 1);
            rs += __shfl_xor_sync(0xffffffffu, rs, 2);
            rs += __shfl_xor_sync(0xffffffffu, rs, 16);
            l_r[i] = l_r[i] * alpha + rs;
            m_r[i] = mn;
            ull al2 = pkdup(alpha);
#pragma unroll
            for (int j = 0; j < 4; j++) mul2(accO2[i][j], al2);
        }
        __syncthreads();   // Ps visible

        // O += P @ V
#pragma unroll 8
        for (int j = 0; j < 64; ++j) {
            ulonglong2 v0 = *(const ulonglong2*)&Vs[j][tx * 8];
            ulonglong2 v1 = *(const ulonglong2*)&Vs[j][tx * 8 + 4];
            ull vb[4] = {v0.x, v0.y, v1.x, v1.y};
#pragma unroll
            for (int i = 0; i < 4; i++) {
                ull pd = pkdup(Ps[ty * 4 + i][j]);
#pragma unroll
                for (int c = 0; c < 4; c++) fma2(accO2[i][c], pd, vb[c]);
            }
        }
    }

    // write O (b, s, h*HD + d)
#pragma unroll
    for (int i = 0; i < 4; i++) {
        float inv = 1.f / l_r[i];
        int row = b * S_LEN + qt * 128 + ty * 4 + i;
        size_t off = (size_t)row * DIM + h * HD + tx * 8;
        float2 u0 = unpk(accO2[i][0]), u1 = unpk(accO2[i][1]);
        float2 u2 = unpk(accO2[i][2]), u3 = unpk(accO2[i][3]);
        *(float4*)&out[off]     = make_float4(u0.x * inv, u0.y * inv, u1.x * inv, u1.y * inv);
        *(float4*)&out[off + 4] = make_float4(u2.x * inv, u2.y * inv, u3.x * inv, u3.y * inv);
    }
}

// ---------------- launcher ----------------
extern "C" void kernel_launch(void* const* d_in, const int* in_sizes, int n_in,
                              void* d_out, int out_size)
{
    const float* x        = (const float*)d_in[0];
    const float* rope_cos = (const float*)d_in[1];
    const float* rope_sin = (const float*)d_in[2];
    const float* n1g      = (const float*)d_in[3];
    const float* n1b      = (const float*)d_in[4];
    const float* n2g      = (const float*)d_in[5];
    const float* n2b      = (const float*)d_in[6];
    const float* w_qkv    = (const float*)d_in[7];
    const float* b_qkv    = (const float*)d_in[8];
    const float* w_proj   = (const float*)d_in[9];
    const float* b_proj   = (const float*)d_in[10];
    const float* w_fc1    = (const float*)d_in[11];
    const float* b_fc1    = (const float*)d_in[12];
    const float* w_fc2    = (const float*)d_in[13];
    const float* b_fc2    = (const float*)d_in[14];
    float* out = (float*)d_out;

    float *ph, *pqkv, *pqt, *pkt, *patt, *px1, *pmid;
    cudaGetSymbolAddress((void**)&ph,   g_h);
    cudaGetSymbolAddress((void**)&pqkv, g_qkv);
    cudaGetSymbolAddress((void**)&pqt,  g_qt);
    cudaGetSymbolAddress((void**)&pkt,  g_kt);
    cudaGetSymbolAddress((void**)&patt, g_att);
    cudaGetSymbolAddress((void**)&px1,  g_x1);
    cudaGetSymbolAddress((void**)&pmid, g_mid);

    cudaFuncSetAttribute(attn_kernel, cudaFuncAttributeMaxDynamicSharedMemorySize,
                         ATT_SMEM_FLOATS * (int)sizeof(float));

    // 1) LN1
    ln_kernel<<<TOK, 256>>>(x, n1g, n1b, ph);
    // 2) QKV GEMM + bias
    gemm_kernel<0><<<dim3(3 * DIM / 128, TOK / 128), 256>>>(ph, w_qkv, b_qkv, nullptr, pqkv,
                                                            TOK, 3 * DIM, DIM);
    // 3) fused RoPE + transpose of Q,K -> [bh][d][s]
    qk_rope_transpose<<<dim3(S_LEN / 32, NB * NH), 256>>>(pqkv, rope_cos, rope_sin,
                                                          pqt, pkt);
    // 4) attention
    attn_kernel<<<dim3(S_LEN / 128, NH, NB), 256, ATT_SMEM_FLOATS * sizeof(float)>>>(
        pqt, pkt, pqkv, patt);
    // 5) proj + bias + residual(x)
    gemm_kernel<2><<<dim3(DIM / 128, TOK / 128), 256>>>(patt, w_proj, b_proj, x, px1,
                                                        TOK, DIM, DIM);
    // 6) LN2
    ln_kernel<<<TOK, 256>>>(px1, n2g, n2b, ph);
    // 7) FC1 + bias + GELU
    gemm_kernel<1><<<dim3(4 * DIM / 128, TOK / 128), 256>>>(ph, w_fc1, b_fc1, nullptr, pmid,
                                                            TOK, 4 * DIM, DIM);
    // 8) FC2 + bias + residual(x1) -> out
    gemm_kernel<2><<<dim3(DIM / 128, TOK / 128), 256>>>(pmid, w_fc2, b_fc2, px1, out,
                                                        TOK, DIM, 4 * DIM);
}